// round 8
// baseline (speedup 1.0000x reference)
#include <cuda_runtime.h>
#include <cuda_fp16.h>
#include <cuda_bf16.h>
#include <cstdint>

#define NN 100000
#define FULL 0xffffffffu
#define CSR_CAP 1900000
#define NB 98           // scan blocks = ceil(NN/1024)

// ---------------- scratch (static __device__, no allocs) ----------------
__device__ __half2 g_h2[NN * 64];    // transformed features [N,128ch] as half2
__device__ float g_s[NN * 4];        // src attention coeff per node/head
__device__ float g_d[NN * 4];        // dst attention coeff per node/head
__device__ float g_f1[NN * 32];      // layer-1 output
__device__ float g_f2[NN * 32];      // layer-2 output
__device__ int   g_deg[NN];          // zero-init at load; re-zeroed by k_scan1 each call
__device__ int   g_start[NN + 1];
__device__ int   g_cursor[NN];
__device__ int   g_csr[CSR_CAP];     // src index per (dst-sorted) edge
__device__ int   g_bsum[NB];

// ---------------- CSR build ----------------
__global__ void k_hist(const int* __restrict__ dst, int E) {
    int i = blockIdx.x * blockDim.x + threadIdx.x;
    if (i < E) atomicAdd(&g_deg[dst[i]], 1);
}

// per-block exclusive scan of (deg+1); zero deg for next call; block total -> g_bsum
__global__ void k_scan1() {
    __shared__ int wsum[32];
    int t = threadIdx.x, lane = t & 31, wid = t >> 5;
    int i = blockIdx.x * 1024 + t;
    int v = 0;
    if (i < NN) { v = g_deg[i] + 1; g_deg[i] = 0; }  // +1 = self loop; reset for next call
    int incl = v;
    #pragma unroll
    for (int off = 1; off < 32; off <<= 1) {
        int u = __shfl_up_sync(FULL, incl, off);
        if (lane >= off) incl += u;
    }
    if (lane == 31) wsum[wid] = incl;
    __syncthreads();
    if (wid == 0) {
        int wv = wsum[lane];
        int wincl = wv;
        #pragma unroll
        for (int off = 1; off < 32; off <<= 1) {
            int u = __shfl_up_sync(FULL, wincl, off);
            if (lane >= off) wincl += u;
        }
        wsum[lane] = wincl - wv;
    }
    __syncthreads();
    int excl = wsum[wid] + incl - v;
    if (i < NN) g_start[i] = excl;
    if (t == 1023) g_bsum[blockIdx.x] = excl + v;
}

// add block offsets (each block re-scans the 98 partials in smem), init cursor,
// write self-loop edge, and write g_start[NN]
__global__ void k_scan3_selfloop() {
    __shared__ int sv[128];
    int t = threadIdx.x;  // 256 threads; first 128 do the partial scan
    if (t < 128) sv[t] = (t < NB) ? g_bsum[t] : 0;
    __syncthreads();
    for (int off = 1; off < 128; off <<= 1) {
        int u = 0;
        if (t < 128 && t >= off) u = sv[t - off];
        __syncthreads();
        if (t < 128) sv[t] += u;
        __syncthreads();
    }
    // sv now inclusive prefix of g_bsum
    int i = blockIdx.x * blockDim.x + t;
    if (i < NN) {
        int chunk = i >> 10;
        int boff = (chunk == 0) ? 0 : sv[chunk - 1];
        int p = g_start[i] + boff;
        g_start[i] = p;
        g_cursor[i] = p + 1;               // next free slot after self loop
        if (p < CSR_CAP) g_csr[p] = i;     // self loop
    }
    if (blockIdx.x == 0 && t == 0) g_start[NN] = sv[NB - 1];
}

__global__ void k_scatter(const int* __restrict__ src, const int* __restrict__ dst, int E) {
    int i = blockIdx.x * blockDim.x + threadIdx.x;
    if (i < E) {
        int pos = atomicAdd(&g_cursor[dst[i]], 1);
        if (pos < CSR_CAP) g_csr[pos] = src[i];
    }
}

// ---------------- transform: h = feat @ W (fp32 math, fp16 store), s/d coeffs fp32 ----------------
template <int K, int LAYER>
__global__ void k_transform(const float* __restrict__ feat_in,
                            const float* __restrict__ W,
                            const float* __restrict__ asrc,
                            const float* __restrict__ adst) {
    const int NPB = 16;
    __shared__ float sW[K * 128];
    __shared__ float sA[256];
    __shared__ float sF[NPB * K];
    const float* feat = (LAYER == 1) ? feat_in : g_f1;
    int t = threadIdx.x;  // 128 threads
    for (int i = t; i < K * 128; i += 128) sW[i] = W[i];
    sA[t]       = asrc[t];
    sA[128 + t] = adst[t];
    int nbase = blockIdx.x * NPB;
    for (int i = t; i < NPB * K; i += 128) {
        long idx = (long)nbase * K + i;
        sF[i] = (idx < (long)NN * K) ? feat[idx] : 0.f;
    }
    __syncthreads();
    int lane = t & 31, hd = t >> 5;
    #pragma unroll
    for (int j = 0; j < NPB; j++) {
        int n = nbase + j;
        if (n >= NN) break;
        float acc = 0.f;
        #pragma unroll
        for (int k = 0; k < K; k++) acc = fmaf(sF[j * K + k], sW[k * 128 + t], acc);
        // pack pairs of channels into half2 (even thread stores t, t+1)
        float hi = __shfl_xor_sync(FULL, acc, 1);
        if ((t & 1) == 0) g_h2[n * 64 + (t >> 1)] = __floats2half2_rn(acc, hi);
        float sv = acc * sA[t];
        float dv = acc * sA[128 + t];
        #pragma unroll
        for (int off = 16; off; off >>= 1) {
            sv += __shfl_xor_sync(FULL, sv, off);
            dv += __shfl_xor_sync(FULL, dv, off);
        }
        if (lane == 0) { g_s[n * 4 + hd] = sv; g_d[n * 4 + hd] = dv; }
    }
}

// ---------------- aggregation: single-pass softmax, fp16 gathers, unroll x4 ----------------
template <int LAYER>
__global__ void k_aggregate(const float* __restrict__ bias) {
    int n = blockIdx.x * (blockDim.x >> 5) + (threadIdx.x >> 5);
    if (n >= NN) return;
    int lane = threadIdx.x & 31;
    int head = lane >> 3;
    int e0 = g_start[n], e1 = g_start[n + 1];
    float dh = g_d[n * 4 + head];

    float ax = 0.f, ay = 0.f, az = 0.f, aw = 0.f;
    float den = 0.f;
    for (int base = e0; base < e1; base += 32) {
        int cnt = min(32, e1 - base);
        int idx = 0;
        if (base + lane < e1) idx = g_csr[base + lane];
        int j = 0;
        for (; j + 3 < cnt; j += 4) {
            int s0 = __shfl_sync(FULL, idx, j);
            int s1 = __shfl_sync(FULL, idx, j + 1);
            int s2 = __shfl_sync(FULL, idx, j + 2);
            int s3 = __shfl_sync(FULL, idx, j + 3);
            float a0 = g_s[s0 * 4 + head] + dh;
            float a1 = g_s[s1 * 4 + head] + dh;
            float a2 = g_s[s2 * 4 + head] + dh;
            float a3 = g_s[s3 * 4 + head] + dh;
            a0 = a0 > 0.f ? a0 : 0.2f * a0;
            a1 = a1 > 0.f ? a1 : 0.2f * a1;
            a2 = a2 > 0.f ? a2 : 0.2f * a2;
            a3 = a3 > 0.f ? a3 : 0.2f * a3;
            float w0 = __expf(a0), w1 = __expf(a1);
            float w2 = __expf(a2), w3 = __expf(a3);
            den += (w0 + w1) + (w2 + w3);
            uint2 u0 = *(const uint2*)(g_h2 + (size_t)s0 * 64 + lane * 2);
            uint2 u1 = *(const uint2*)(g_h2 + (size_t)s1 * 64 + lane * 2);
            uint2 u2 = *(const uint2*)(g_h2 + (size_t)s2 * 64 + lane * 2);
            uint2 u3 = *(const uint2*)(g_h2 + (size_t)s3 * 64 + lane * 2);
            float2 p0 = __half22float2(*(__half2*)&u0.x);
            float2 q0 = __half22float2(*(__half2*)&u0.y);
            float2 p1 = __half22float2(*(__half2*)&u1.x);
            float2 q1 = __half22float2(*(__half2*)&u1.y);
            float2 p2 = __half22float2(*(__half2*)&u2.x);
            float2 q2 = __half22float2(*(__half2*)&u2.y);
            float2 p3 = __half22float2(*(__half2*)&u3.x);
            float2 q3 = __half22float2(*(__half2*)&u3.y);
            ax = fmaf(w0, p0.x, ax); ay = fmaf(w0, p0.y, ay);
            az = fmaf(w0, q0.x, az); aw = fmaf(w0, q0.y, aw);
            ax = fmaf(w1, p1.x, ax); ay = fmaf(w1, p1.y, ay);
            az = fmaf(w1, q1.x, az); aw = fmaf(w1, q1.y, aw);
            ax = fmaf(w2, p2.x, ax); ay = fmaf(w2, p2.y, ay);
            az = fmaf(w2, q2.x, az); aw = fmaf(w2, q2.y, aw);
            ax = fmaf(w3, p3.x, ax); ay = fmaf(w3, p3.y, ay);
            az = fmaf(w3, q3.x, az); aw = fmaf(w3, q3.y, aw);
        }
        for (; j < cnt; j++) {
            int s = __shfl_sync(FULL, idx, j);
            float a = g_s[s * 4 + head] + dh;
            a = a > 0.f ? a : 0.2f * a;
            float w = __expf(a);
            den += w;
            uint2 u = *(const uint2*)(g_h2 + (size_t)s * 64 + lane * 2);
            float2 p = __half22float2(*(__half2*)&u.x);
            float2 q = __half22float2(*(__half2*)&u.y);
            ax = fmaf(w, p.x, ax); ay = fmaf(w, p.y, ay);
            az = fmaf(w, q.x, az); aw = fmaf(w, q.y, aw);
        }
    }
    float inv = 0.25f / den;
    ax *= inv; ay *= inv; az *= inv; aw *= inv;
    #pragma unroll
    for (int off = 8; off <= 16; off <<= 1) {
        ax += __shfl_xor_sync(FULL, ax, off);
        ay += __shfl_xor_sync(FULL, ay, off);
        az += __shfl_xor_sync(FULL, az, off);
        aw += __shfl_xor_sync(FULL, aw, off);
    }
    if (lane < 8) {
        float4 bv = ((const float4*)bias)[lane];
        float4 o;
        o.x = fmaxf(ax + bv.x, 0.f);
        o.y = fmaxf(ay + bv.y, 0.f);
        o.z = fmaxf(az + bv.z, 0.f);
        o.w = fmaxf(aw + bv.w, 0.f);
        float* dstp = (LAYER == 1) ? g_f1 : g_f2;
        *(float4*)(dstp + n * 32 + lane * 4) = o;
    }
}

// ---------------- node logits ----------------
__global__ void k_node_logits(const float* __restrict__ Wn,
                              const float* __restrict__ bn,
                              float* __restrict__ out) {
    int n = blockIdx.x * blockDim.x + threadIdx.x;
    if (n >= NN) return;
    float o0 = bn[0], o1 = bn[1];
    const float4* fp = (const float4*)(g_f2 + n * 32);
    #pragma unroll
    for (int q = 0; q < 8; q++) {
        float4 v = fp[q];
        int k = q * 4;
        o0 = fmaf(v.x, __ldg(&Wn[k * 2]),       o0);
        o1 = fmaf(v.x, __ldg(&Wn[k * 2 + 1]),   o1);
        o0 = fmaf(v.y, __ldg(&Wn[(k+1) * 2]),   o0);
        o1 = fmaf(v.y, __ldg(&Wn[(k+1) * 2+1]), o1);
        o0 = fmaf(v.z, __ldg(&Wn[(k+2) * 2]),   o0);
        o1 = fmaf(v.z, __ldg(&Wn[(k+2) * 2+1]), o1);
        o0 = fmaf(v.w, __ldg(&Wn[(k+3) * 2]),   o0);
        o1 = fmaf(v.w, __ldg(&Wn[(k+3) * 2+1]), o1);
    }
    out[n * 2]     = o0;
    out[n * 2 + 1] = o1;
}

// ---------------- edge MLP via mma.sync m16n8k8 TF32 ----------------
__device__ __forceinline__ unsigned int f2tf32(float f) {
    unsigned int u;
    asm("cvt.rna.tf32.f32 %0, %1;" : "=r"(u) : "f"(f));
    return u;
}

#define SW_STRIDE 72

__global__ void k_edge_mlp_mma(const int* __restrict__ ea,
                               const int* __restrict__ eb, int EL,
                               const float* __restrict__ We1,
                               const float* __restrict__ be1,
                               const float* __restrict__ We2,
                               const float* __restrict__ be2,
                               float* __restrict__ out) {
    __shared__ unsigned int sW[64 * SW_STRIDE];   // We1 as tf32 bits, [k][n] padded
    __shared__ float sB[64];                      // be1
    __shared__ float sV[64];                      // We2
    int t = threadIdx.x;  // 128
    for (int i = t; i < 64 * 64; i += 128) {
        int k = i >> 6, n = i & 63;
        sW[k * SW_STRIDE + n] = f2tf32(We1[i]);
    }
    if (t < 64) { sB[t] = be1[t]; sV[t] = We2[t]; }
    float bb2 = be2[0];
    __syncthreads();

    int lane = t & 31;
    int g = lane >> 2;       // 0..7
    int tg = lane & 3;       // 0..3
    int ntiles = (EL + 15) >> 4;
    int nwarps = gridDim.x * (blockDim.x >> 5);
    int w = blockIdx.x * (blockDim.x >> 5) + (t >> 5);

    for (int tile = w; tile < ntiles; tile += nwarps) {
        int e0 = tile << 4;
        int ra = 0, rb = 0;
        if (lane < 16) {
            int e = e0 + lane;
            if (e < EL) { ra = ea[e]; rb = eb[e]; }
        }
        int iaG  = __shfl_sync(FULL, ra, g);
        int iaG8 = __shfl_sync(FULL, ra, g + 8);
        int ibG  = __shfl_sync(FULL, rb, g);
        int ibG8 = __shfl_sync(FULL, rb, g + 8);
        const float* pA0 = g_f2 + (size_t)iaG  * 32;
        const float* pA1 = g_f2 + (size_t)iaG8 * 32;
        const float* pB0 = g_f2 + (size_t)ibG  * 32;
        const float* pB1 = g_f2 + (size_t)ibG8 * 32;

        unsigned int A0[8], A1[8], A2[8], A3[8];
        #pragma unroll
        for (int kc = 0; kc < 4; kc++) {
            int c = kc * 8 + tg;
            A0[kc] = f2tf32(pA0[c]);
            A1[kc] = f2tf32(pA1[c]);
            A2[kc] = f2tf32(pA0[c + 4]);
            A3[kc] = f2tf32(pA1[c + 4]);
        }
        #pragma unroll
        for (int kc = 4; kc < 8; kc++) {
            int c = (kc - 4) * 8 + tg;
            A0[kc] = f2tf32(pB0[c]);
            A1[kc] = f2tf32(pB1[c]);
            A2[kc] = f2tf32(pB0[c + 4]);
            A3[kc] = f2tf32(pB1[c + 4]);
        }

        float pg = 0.f, pg8 = 0.f;
        #pragma unroll
        for (int nc = 0; nc < 8; nc++) {
            float c0 = 0.f, c1 = 0.f, c2 = 0.f, c3 = 0.f;
            int n0 = nc * 8 + g;
            #pragma unroll
            for (int kc = 0; kc < 8; kc++) {
                unsigned int b0 = sW[(kc * 8 + tg) * SW_STRIDE + n0];
                unsigned int b1 = sW[(kc * 8 + tg + 4) * SW_STRIDE + n0];
                asm volatile(
                    "mma.sync.aligned.m16n8k8.row.col.f32.tf32.tf32.f32 "
                    "{%0,%1,%2,%3},{%4,%5,%6,%7},{%8,%9},{%0,%1,%2,%3};"
                    : "+f"(c0), "+f"(c1), "+f"(c2), "+f"(c3)
                    : "r"(A0[kc]), "r"(A1[kc]), "r"(A2[kc]), "r"(A3[kc]),
                      "r"(b0), "r"(b1));
            }
            int col0 = nc * 8 + 2 * tg;
            float bi0 = sB[col0], bi1 = sB[col0 + 1];
            float v0 = sV[col0],  v1 = sV[col0 + 1];
            pg  = fmaf(fmaxf(c0 + bi0, 0.f), v0, pg);
            pg  = fmaf(fmaxf(c1 + bi1, 0.f), v1, pg);
            pg8 = fmaf(fmaxf(c2 + bi0, 0.f), v0, pg8);
            pg8 = fmaf(fmaxf(c3 + bi1, 0.f), v1, pg8);
        }
        pg  += __shfl_xor_sync(FULL, pg, 1);
        pg  += __shfl_xor_sync(FULL, pg, 2);
        pg8 += __shfl_xor_sync(FULL, pg8, 1);
        pg8 += __shfl_xor_sync(FULL, pg8, 2);
        if (tg == 0) {
            if (e0 + g < EL)     out[e0 + g]     = pg + bb2;
            if (e0 + g + 8 < EL) out[e0 + g + 8] = pg8 + bb2;
        }
    }
}

// ---------------- launch: ONLY kernel launches ----------------
extern "C" void kernel_launch(void* const* d_in, const int* in_sizes, int n_in,
                              void* d_out, int out_size) {
    const float* x    = (const float*)d_in[0];
    const int*   ei   = (const int*)d_in[1];
    const int*   eli  = (const int*)d_in[2];
    const float* W1   = (const float*)d_in[3];
    const float* as1  = (const float*)d_in[4];
    const float* ad1  = (const float*)d_in[5];
    const float* b1   = (const float*)d_in[6];
    const float* W2   = (const float*)d_in[7];
    const float* as2  = (const float*)d_in[8];
    const float* ad2  = (const float*)d_in[9];
    const float* b2   = (const float*)d_in[10];
    const float* Wn   = (const float*)d_in[11];
    const float* bn   = (const float*)d_in[12];
    const float* We1  = (const float*)d_in[13];
    const float* be1  = (const float*)d_in[14];
    const float* We2  = (const float*)d_in[15];
    const float* be2  = (const float*)d_in[16];
    float* out = (float*)d_out;

    int E  = in_sizes[1] / 2;
    int EL = in_sizes[2] / 2;
    const int* src  = ei;
    const int* dst  = ei + E;
    const int* ea   = eli;
    const int* eb   = eli + EL;

    // CSR build
    k_hist<<<(E + 255) / 256, 256>>>(dst, E);
    k_scan1<<<NB, 1024>>>();
    k_scan3_selfloop<<<(NN + 255) / 256, 256>>>();
    k_scatter<<<(E + 255) / 256, 256>>>(src, dst, E);

    const int TGRID = (NN + 15) / 16;  // 16 nodes per block
    const int AGRID = (NN + 7) / 8;    // 8 warps per block, 1 node per warp

    // layer 1
    k_transform<9, 1><<<TGRID, 128>>>(x, W1, as1, ad1);
    k_aggregate<1><<<AGRID, 256>>>(b1);
    // layer 2
    k_transform<32, 2><<<TGRID, 128>>>(nullptr, W2, as2, ad2);
    k_aggregate<2><<<AGRID, 256>>>(b2);

    // heads
    k_node_logits<<<(NN + 255) / 256, 256>>>(Wn, bn, out);
    k_edge_mlp_mma<<<592, 128>>>(ea, eb, EL, We1, be1, We2, be2, out + NN * 2);
}

// round 10
// speedup vs baseline: 1.0583x; 1.0583x over previous
#include <cuda_runtime.h>
#include <cuda_fp16.h>
#include <cuda_bf16.h>
#include <cstdint>

#define NN 100000
#define FULL 0xffffffffu
#define CSR_CAP 1900000
#define NB 98           // scan blocks = ceil(NN/1024)

// ---------------- scratch (static __device__, no allocs) ----------------
__device__ __half2 g_h2[NN * 64];    // transformed features [N,128ch] as half2
__device__ float g_s[NN * 4];        // src attention coeff per node/head
__device__ float g_d[NN * 4];        // dst attention coeff per node/head
__device__ float g_f1[NN * 32];      // layer-1 output
__device__ float g_f2[NN * 32];      // layer-2 output
__device__ int   g_deg[NN];          // zero-init at load; re-zeroed by k_scan1 each call
__device__ int   g_start[NN + 1];
__device__ int   g_cursor[NN];
__device__ int   g_csr[CSR_CAP];     // src index per (dst-sorted) edge
__device__ int   g_bsum[NB];

// ---------------- CSR build ----------------
__global__ void k_hist(const int* __restrict__ dst, int E) {
    int i = blockIdx.x * blockDim.x + threadIdx.x;
    if (i < E) atomicAdd(&g_deg[dst[i]], 1);
}

// per-block exclusive scan of (deg+1); zero deg for next call; block total -> g_bsum
__global__ void k_scan1() {
    __shared__ int wsum[32];
    int t = threadIdx.x, lane = t & 31, wid = t >> 5;
    int i = blockIdx.x * 1024 + t;
    int v = 0;
    if (i < NN) { v = g_deg[i] + 1; g_deg[i] = 0; }
    int incl = v;
    #pragma unroll
    for (int off = 1; off < 32; off <<= 1) {
        int u = __shfl_up_sync(FULL, incl, off);
        if (lane >= off) incl += u;
    }
    if (lane == 31) wsum[wid] = incl;
    __syncthreads();
    if (wid == 0) {
        int wv = wsum[lane];
        int wincl = wv;
        #pragma unroll
        for (int off = 1; off < 32; off <<= 1) {
            int u = __shfl_up_sync(FULL, wincl, off);
            if (lane >= off) wincl += u;
        }
        wsum[lane] = wincl - wv;
    }
    __syncthreads();
    int excl = wsum[wid] + incl - v;
    if (i < NN) g_start[i] = excl;
    if (t == 1023) g_bsum[blockIdx.x] = excl + v;
}

// add block offsets (each block re-scans the 98 partials in smem), init cursor,
// write self-loop edge, write g_start[NN]
__global__ void k_scan3_selfloop() {
    __shared__ int sv[128];
    int t = threadIdx.x;  // 256 threads; first 128 do the partial scan
    if (t < 128) sv[t] = (t < NB) ? g_bsum[t] : 0;
    __syncthreads();
    for (int off = 1; off < 128; off <<= 1) {
        int u = 0;
        if (t < 128 && t >= off) u = sv[t - off];
        __syncthreads();
        if (t < 128) sv[t] += u;
        __syncthreads();
    }
    int i = blockIdx.x * blockDim.x + t;
    if (i < NN) {
        int chunk = i >> 10;
        int boff = (chunk == 0) ? 0 : sv[chunk - 1];
        int p = g_start[i] + boff;
        g_start[i] = p;
        g_cursor[i] = p + 1;
        if (p < CSR_CAP) g_csr[p] = i;
    }
    if (blockIdx.x == 0 && t == 0) g_start[NN] = sv[NB - 1];
}

__global__ void k_scatter(const int* __restrict__ src, const int* __restrict__ dst, int E) {
    int i = blockIdx.x * blockDim.x + threadIdx.x;
    if (i < E) {
        int pos = atomicAdd(&g_cursor[dst[i]], 1);
        if (pos < CSR_CAP) g_csr[pos] = src[i];
    }
}

// ---------------- transform: h = feat @ W (fp32 math, fp16 store), s/d coeffs fp32 ----------------
template <int K, int LAYER>
__global__ void k_transform(const float* __restrict__ feat_in,
                            const float* __restrict__ W,
                            const float* __restrict__ asrc,
                            const float* __restrict__ adst) {
    const int NPB = 16;
    __shared__ float sW[K * 128];
    __shared__ float sA[256];
    __shared__ float sF[NPB * K];
    const float* feat = (LAYER == 1) ? feat_in : g_f1;
    int t = threadIdx.x;  // 128 threads
    for (int i = t; i < K * 128; i += 128) sW[i] = W[i];
    sA[t]       = asrc[t];
    sA[128 + t] = adst[t];
    int nbase = blockIdx.x * NPB;
    for (int i = t; i < NPB * K; i += 128) {
        long idx = (long)nbase * K + i;
        sF[i] = (idx < (long)NN * K) ? feat[idx] : 0.f;
    }
    __syncthreads();
    int lane = t & 31, hd = t >> 5;
    #pragma unroll
    for (int j = 0; j < NPB; j++) {
        int n = nbase + j;
        if (n >= NN) break;
        float acc = 0.f;
        #pragma unroll
        for (int k = 0; k < K; k++) acc = fmaf(sF[j * K + k], sW[k * 128 + t], acc);
        float hi = __shfl_xor_sync(FULL, acc, 1);
        if ((t & 1) == 0) g_h2[n * 64 + (t >> 1)] = __floats2half2_rn(acc, hi);
        float sv = acc * sA[t];
        float dv = acc * sA[128 + t];
        #pragma unroll
        for (int off = 16; off; off >>= 1) {
            sv += __shfl_xor_sync(FULL, sv, off);
            dv += __shfl_xor_sync(FULL, dv, off);
        }
        if (lane == 0) { g_s[n * 4 + hd] = sv; g_d[n * 4 + hd] = dv; }
    }
}

// ---------------- aggregation: paired-edge LDG.128 gathers ----------------
// 16 lanes cover one node row (uint4 = 8 fp16 channels each); the two half-warps
// process two different edges per step. Softmax without max-shift.
__device__ __forceinline__ void acc8(float* acc, float w, const uint4& u) {
    float2 t0 = __half22float2(*(const __half2*)&u.x);
    float2 t1 = __half22float2(*(const __half2*)&u.y);
    float2 t2 = __half22float2(*(const __half2*)&u.z);
    float2 t3 = __half22float2(*(const __half2*)&u.w);
    acc[0] = fmaf(w, t0.x, acc[0]); acc[1] = fmaf(w, t0.y, acc[1]);
    acc[2] = fmaf(w, t1.x, acc[2]); acc[3] = fmaf(w, t1.y, acc[3]);
    acc[4] = fmaf(w, t2.x, acc[4]); acc[5] = fmaf(w, t2.y, acc[5]);
    acc[6] = fmaf(w, t3.x, acc[6]); acc[7] = fmaf(w, t3.y, acc[7]);
}

template <int LAYER>
__global__ void k_aggregate(const float* __restrict__ bias,
                            const float* __restrict__ Wn,
                            const float* __restrict__ bn,
                            float* __restrict__ nodeout) {
    int n = blockIdx.x * (blockDim.x >> 5) + (threadIdx.x >> 5);
    if (n >= NN) return;
    int lane = threadIdx.x & 31;
    int half = lane >> 4;       // which edge of the pair
    int sub  = lane & 15;       // channel-group owner: channels [8*sub, 8*sub+8)
    int head = sub >> 2;
    int e0 = g_start[n], e1 = g_start[n + 1];
    float dh = g_d[n * 4 + head];

    float acc[8] = {0.f, 0.f, 0.f, 0.f, 0.f, 0.f, 0.f, 0.f};
    float den = 0.f;
    for (int base = e0; base < e1; base += 32) {
        int cnt = min(32, e1 - base);
        int idx = 0;
        if (base + lane < e1) idx = g_csr[base + lane];
        int j = 0;
        for (; j + 3 < cnt; j += 4) {
            int sA = __shfl_sync(FULL, idx, j + half);
            int sB = __shfl_sync(FULL, idx, j + 2 + half);
            float aA = g_s[sA * 4 + head] + dh;
            float aB = g_s[sB * 4 + head] + dh;
            uint4 uA = ((const uint4*)(g_h2 + (size_t)sA * 64))[sub];
            uint4 uB = ((const uint4*)(g_h2 + (size_t)sB * 64))[sub];
            aA = aA > 0.f ? aA : 0.2f * aA;
            aB = aB > 0.f ? aB : 0.2f * aB;
            float wA = __expf(aA), wB = __expf(aB);
            den += wA + wB;
            acc8(acc, wA, uA);
            acc8(acc, wB, uB);
        }
        for (; j < cnt; j += 2) {
            int e = j + half;
            int ec = e < cnt ? e : cnt - 1;
            int s = __shfl_sync(FULL, idx, ec);
            float a = g_s[s * 4 + head] + dh;
            a = a > 0.f ? a : 0.2f * a;
            float w = (e < cnt) ? __expf(a) : 0.f;
            uint4 u = ((const uint4*)(g_h2 + (size_t)s * 64))[sub];
            den += w;
            acc8(acc, w, u);
        }
    }
    // combine the two half-warps (same channels, disjoint edge subsets)
    den += __shfl_xor_sync(FULL, den, 16);
    #pragma unroll
    for (int i = 0; i < 8; i++) acc[i] += __shfl_xor_sync(FULL, acc[i], 16);
    // per-head normalize, then sum heads (lanes sub, sub+4, sub+8, sub+12 share inner channels)
    float inv = 0.25f / den;
    #pragma unroll
    for (int i = 0; i < 8; i++) acc[i] *= inv;
    #pragma unroll
    for (int i = 0; i < 8; i++) {
        acc[i] += __shfl_xor_sync(FULL, acc[i], 4);
        acc[i] += __shfl_xor_sync(FULL, acc[i], 8);
    }
    // lanes sub<4 hold channels [sub*8, sub*8+8)
    float o[8];
    if (sub < 4) {
        float4 b0 = ((const float4*)bias)[sub * 2];
        float4 b1 = ((const float4*)bias)[sub * 2 + 1];
        o[0] = fmaxf(acc[0] + b0.x, 0.f);
        o[1] = fmaxf(acc[1] + b0.y, 0.f);
        o[2] = fmaxf(acc[2] + b0.z, 0.f);
        o[3] = fmaxf(acc[3] + b0.w, 0.f);
        o[4] = fmaxf(acc[4] + b1.x, 0.f);
        o[5] = fmaxf(acc[5] + b1.y, 0.f);
        o[6] = fmaxf(acc[6] + b1.z, 0.f);
        o[7] = fmaxf(acc[7] + b1.w, 0.f);
        if (half == 0) {
            float* dstp = (LAYER == 1) ? g_f1 : g_f2;
            float4 w0 = make_float4(o[0], o[1], o[2], o[3]);
            float4 w1 = make_float4(o[4], o[5], o[6], o[7]);
            *(float4*)(dstp + n * 32 + sub * 8)     = w0;
            *(float4*)(dstp + n * 32 + sub * 8 + 4) = w1;
        }
    } else {
        #pragma unroll
        for (int i = 0; i < 8; i++) o[i] = 0.f;
    }
    if (LAYER == 2) {
        // fused node logits: out[n] = f2[n] @ Wn + bn
        float p0 = 0.f, p1 = 0.f;
        if (sub < 4) {
            #pragma unroll
            for (int i = 0; i < 8; i++) {
                int c = sub * 8 + i;
                p0 = fmaf(o[i], __ldg(&Wn[c * 2]),     p0);
                p1 = fmaf(o[i], __ldg(&Wn[c * 2 + 1]), p1);
            }
        }
        p0 += __shfl_xor_sync(FULL, p0, 1);
        p0 += __shfl_xor_sync(FULL, p0, 2);
        p1 += __shfl_xor_sync(FULL, p1, 1);
        p1 += __shfl_xor_sync(FULL, p1, 2);
        if (lane == 0) {
            nodeout[n * 2]     = p0 + bn[0];
            nodeout[n * 2 + 1] = p1 + bn[1];
        }
    }
}

// ---------------- edge MLP via mma.sync m16n8k8 TF32 ----------------
__device__ __forceinline__ unsigned int f2tf32(float f) {
    unsigned int u;
    asm("cvt.rna.tf32.f32 %0, %1;" : "=r"(u) : "f"(f));
    return u;
}

#define SW_STRIDE 72

__global__ void k_edge_mlp_mma(const int* __restrict__ ea,
                               const int* __restrict__ eb, int EL,
                               const float* __restrict__ We1,
                               const float* __restrict__ be1,
                               const float* __restrict__ We2,
                               const float* __restrict__ be2,
                               float* __restrict__ out) {
    __shared__ unsigned int sW[64 * SW_STRIDE];
    __shared__ float sB[64];
    __shared__ float sV[64];
    int t = threadIdx.x;  // 128
    for (int i = t; i < 64 * 64; i += 128) {
        int k = i >> 6, n = i & 63;
        sW[k * SW_STRIDE + n] = f2tf32(We1[i]);
    }
    if (t < 64) { sB[t] = be1[t]; sV[t] = We2[t]; }
    float bb2 = be2[0];
    __syncthreads();

    int lane = t & 31;
    int g = lane >> 2;
    int tg = lane & 3;
    int ntiles = (EL + 15) >> 4;
    int nwarps = gridDim.x * (blockDim.x >> 5);
    int w = blockIdx.x * (blockDim.x >> 5) + (t >> 5);

    for (int tile = w; tile < ntiles; tile += nwarps) {
        int e0 = tile << 4;
        int ra = 0, rb = 0;
        if (lane < 16) {
            int e = e0 + lane;
            if (e < EL) { ra = ea[e]; rb = eb[e]; }
        }
        int iaG  = __shfl_sync(FULL, ra, g);
        int iaG8 = __shfl_sync(FULL, ra, g + 8);
        int ibG  = __shfl_sync(FULL, rb, g);
        int ibG8 = __shfl_sync(FULL, rb, g + 8);
        const float* pA0 = g_f2 + (size_t)iaG  * 32;
        const float* pA1 = g_f2 + (size_t)iaG8 * 32;
        const float* pB0 = g_f2 + (size_t)ibG  * 32;
        const float* pB1 = g_f2 + (size_t)ibG8 * 32;

        unsigned int A0[8], A1[8], A2[8], A3[8];
        #pragma unroll
        for (int kc = 0; kc < 4; kc++) {
            int c = kc * 8 + tg;
            A0[kc] = f2tf32(pA0[c]);
            A1[kc] = f2tf32(pA1[c]);
            A2[kc] = f2tf32(pA0[c + 4]);
            A3[kc] = f2tf32(pA1[c + 4]);
        }
        #pragma unroll
        for (int kc = 4; kc < 8; kc++) {
            int c = (kc - 4) * 8 + tg;
            A0[kc] = f2tf32(pB0[c]);
            A1[kc] = f2tf32(pB1[c]);
            A2[kc] = f2tf32(pB0[c + 4]);
            A3[kc] = f2tf32(pB1[c + 4]);
        }

        float pg = 0.f, pg8 = 0.f;
        #pragma unroll
        for (int nc = 0; nc < 8; nc++) {
            float c0 = 0.f, c1 = 0.f, c2 = 0.f, c3 = 0.f;
            int n0 = nc * 8 + g;
            #pragma unroll
            for (int kc = 0; kc < 8; kc++) {
                unsigned int b0 = sW[(kc * 8 + tg) * SW_STRIDE + n0];
                unsigned int b1 = sW[(kc * 8 + tg + 4) * SW_STRIDE + n0];
                asm volatile(
                    "mma.sync.aligned.m16n8k8.row.col.f32.tf32.tf32.f32 "
                    "{%0,%1,%2,%3},{%4,%5,%6,%7},{%8,%9},{%0,%1,%2,%3};"
                    : "+f"(c0), "+f"(c1), "+f"(c2), "+f"(c3)
                    : "r"(A0[kc]), "r"(A1[kc]), "r"(A2[kc]), "r"(A3[kc]),
                      "r"(b0), "r"(b1));
            }
            int col0 = nc * 8 + 2 * tg;
            float bi0 = sB[col0], bi1 = sB[col0 + 1];
            float v0 = sV[col0],  v1 = sV[col0 + 1];
            pg  = fmaf(fmaxf(c0 + bi0, 0.f), v0, pg);
            pg  = fmaf(fmaxf(c1 + bi1, 0.f), v1, pg);
            pg8 = fmaf(fmaxf(c2 + bi0, 0.f), v0, pg8);
            pg8 = fmaf(fmaxf(c3 + bi1, 0.f), v1, pg8);
        }
        pg  += __shfl_xor_sync(FULL, pg, 1);
        pg  += __shfl_xor_sync(FULL, pg, 2);
        pg8 += __shfl_xor_sync(FULL, pg8, 1);
        pg8 += __shfl_xor_sync(FULL, pg8, 2);
        if (tg == 0) {
            if (e0 + g < EL)     out[e0 + g]     = pg + bb2;
            if (e0 + g + 8 < EL) out[e0 + g + 8] = pg8 + bb2;
        }
    }
}

// ---------------- launch: ONLY kernel launches ----------------
extern "C" void kernel_launch(void* const* d_in, const int* in_sizes, int n_in,
                              void* d_out, int out_size) {
    const float* x    = (const float*)d_in[0];
    const int*   ei   = (const int*)d_in[1];
    const int*   eli  = (const int*)d_in[2];
    const float* W1   = (const float*)d_in[3];
    const float* as1  = (const float*)d_in[4];
    const float* ad1  = (const float*)d_in[5];
    const float* b1   = (const float*)d_in[6];
    const float* W2   = (const float*)d_in[7];
    const float* as2  = (const float*)d_in[8];
    const float* ad2  = (const float*)d_in[9];
    const float* b2   = (const float*)d_in[10];
    const float* Wn   = (const float*)d_in[11];
    const float* bn   = (const float*)d_in[12];
    const float* We1  = (const float*)d_in[13];
    const float* be1  = (const float*)d_in[14];
    const float* We2  = (const float*)d_in[15];
    const float* be2  = (const float*)d_in[16];
    float* out = (float*)d_out;

    int E  = in_sizes[1] / 2;
    int EL = in_sizes[2] / 2;
    const int* src  = ei;
    const int* dst  = ei + E;
    const int* ea   = eli;
    const int* eb   = eli + EL;

    // CSR build
    k_hist<<<(E + 255) / 256, 256>>>(dst, E);
    k_scan1<<<NB, 1024>>>();
    k_scan3_selfloop<<<(NN + 255) / 256, 256>>>();
    k_scatter<<<(E + 255) / 256, 256>>>(src, dst, E);

    const int TGRID = (NN + 15) / 16;  // 16 nodes per block
    const int AGRID = (NN + 7) / 8;    // 8 warps per block, 1 node per warp

    // layer 1
    k_transform<9, 1><<<TGRID, 128>>>(x, W1, as1, ad1);
    k_aggregate<1><<<AGRID, 256>>>(b1, nullptr, nullptr, nullptr);
    // layer 2 (+ fused node logits)
    k_transform<32, 2><<<TGRID, 128>>>(nullptr, W2, as2, ad2);
    k_aggregate<2><<<AGRID, 256>>>(b2, Wn, bn, out);

    // edge MLP head
    k_edge_mlp_mma<<<592, 128>>>(ea, eb, EL, We1, be1, We2, be2, out + NN * 2);
}